// round 15
// baseline (speedup 1.0000x reference)
// Round 15: round-13 PDL champion (2230.7us) + explicit early trigger ONLY in
// k_gates (short, low-occupancy primary) so conv(t+1)'s prologue overlaps the
// whole gates body. k_conv keeps the implicit trigger (round-14 showed an early
// conv trigger lets gates blocks contend with the conv mainloop and regresses).
#include <cuda_runtime.h>
#include <math.h>

#define BB   64
#define TT   32
#define HID  3
#define G    64
#define GG   4096
#define NOC  12
#define EPSV 1e-5f
#define FK   37
#define OUTW 28

typedef unsigned long long u64;

// ---------------- packed f32x2 helpers (Blackwell FFMA2 path) ----------------
__device__ __forceinline__ u64 pack2(float x) {
    u64 d; unsigned u = __float_as_uint(x);
    asm("mov.b64 %0, {%1, %1};" : "=l"(d) : "r"(u));
    return d;
}
__device__ __forceinline__ u64 packlh(float lo, float hi) {
    u64 d; unsigned a = __float_as_uint(lo), b = __float_as_uint(hi);
    asm("mov.b64 %0, {%1, %2};" : "=l"(d) : "r"(a), "r"(b));
    return d;
}
__device__ __forceinline__ void ffma2(u64 &acc, u64 a, u64 b) {
    asm("fma.rn.f32x2 %0, %1, %2, %0;" : "+l"(acc) : "l"(a), "l"(b));
}
__device__ __forceinline__ void unpack2(u64 d, float &lo, float &hi) {
    unsigned a, b;
    asm("mov.b64 {%0, %1}, %2;" : "=r"(a), "=r"(b) : "l"(d));
    lo = __uint_as_float(a); hi = __uint_as_float(b);
}

// fast sigmoid / tanh (~1e-6 rel err)
__device__ __forceinline__ float fsig(float x) {
    float t, r;
    asm("mul.f32 %0, %1, 0fBFB8AA3B;" : "=f"(t) : "f"(x));
    asm("ex2.approx.f32 %0, %0;" : "+f"(t));
    asm("add.f32 %0, %0, 0f3F800000;" : "+f"(t));
    asm("rcp.approx.f32 %0, %1;" : "=f"(r) : "f"(t));
    return r;
}
__device__ __forceinline__ float ftanh(float x) {
    return fmaf(2.f, fsig(2.f * x), -1.f);
}

// ---------------- static device scratch ----------------
__device__ float g_h[BB*HID*GG];
__device__ float g_c[BB*HID*GG];
__device__ float g_z[BB*NOC*GG];
__device__ float g_part[BB*8*2*4];   // [b][tile][half][gate_local*2+which]

__global__ void k_init() {
    int i = blockIdx.x * blockDim.x + threadIdx.x;
    if (i < BB*HID*GG) { g_h[i] = 0.f; g_c[i] = 0.f; }
}

// ---------------- per-step conv, oc-halves + PDL (implicit trigger) ------------
// grid: BB*16 blocks = (b, tile 0..7, half 0..1); 16x32 output tile, 128 thr, 4 px
__global__ __launch_bounds__(128, 7) void k_conv(const float* __restrict__ x,
                                                 const float* __restrict__ Wg,
                                                 const float* __restrict__ bg,
                                                 int t)
{
    __shared__ __align__(16) float ts[4*26*44];     // input tile, row stride 44 (18.3KB)
    __shared__ __align__(16) float wsm[4*121*6];    // weights [ic][ky][kx][ocl] (11.6KB)
    __shared__ float sred[4][4];

    const int tid  = threadIdx.x;
    const int b    = blockIdx.x >> 4;
    const int rem  = blockIdx.x & 15;
    const int tile = rem >> 1;                    // 0..7: 4 row-tiles x 2 col-tiles
    const int half = rem & 1;
    const int ty0  = (tile >> 1) << 4;            // 0,16,32,48
    const int tx0  = (tile & 1) << 5;             // 0,32

    // ---- PDL prologue (independent of predecessor kernel) ----
    for (int i = tid; i < 4*121*6; i += 128) {
        int ocl = i % 6;
        int k   = i / 6;
        int ic  = k / 121;
        int kk  = k - ic*121;
        wsm[i] = Wg[((half*6 + ocl)*4 + ic)*121 + kk];
    }
    const float* xb = x + (size_t)(b*TT + t) * GG;
    for (int i = tid; i < 1092; i += 128) {
        int r  = i / 42;
        int cc = i - r*42;
        int gy = ty0 - 5 + r;
        int gx = tx0 - 5 + cc;
        float v = 0.f;
        if (gy >= 0 && gy < G && gx >= 0 && gx < G) v = xb[gy*G + gx];
        ts[r*44 + cc] = v;
    }

    // ---- wait for predecessor (gates t-1 / init) before touching g_h ----
    cudaGridDependencySynchronize();

    // ic = 1..3 tile rows from g_h
    for (int i = tid; i < 3*1092; i += 128) {
        int ic  = i / 1092 + 1;
        int rm  = i - (ic - 1)*1092;
        int r   = rm / 42;
        int cc  = rm - r*42;
        int gy = ty0 - 5 + r;
        int gx = tx0 - 5 + cc;
        float v = 0.f;
        if (gy >= 0 && gy < G && gx >= 0 && gx < G)
            v = g_h[(b*HID + ic - 1)*GG + gy*G + gx];
        ts[(ic*26 + r)*44 + cc] = v;
    }
    __syncthreads();

    const int ty  = tid >> 3;           // 0..15
    const int tx4 = (tid & 7) << 2;     // 0,4,..,28

    u64 acc[4][3];
    #pragma unroll
    for (int j = 0; j < 3; j++) {
        u64 bp = packlh(bg[half*6 + 2*j], bg[half*6 + 2*j + 1]);
        #pragma unroll
        for (int p = 0; p < 4; p++) acc[p][j] = bp;
    }

    #pragma unroll 1
    for (int ic = 0; ic < 4; ic++) {
        #pragma unroll 1
        for (int ky = 0; ky < 11; ky++) {
            const float* rowp = &ts[(ic*26 + ty + ky)*44 + tx4];
            const u64*   wp   = (const u64*)&wsm[(ic*121 + ky*11)*6];

            // --- section 1: kx = 0..5, inputs [0..8] ---
            {
                u64 winp[9];
                {
                    float4 a = ((const float4*)rowp)[0];
                    float4 c = ((const float4*)rowp)[1];
                    float  e = rowp[8];
                    winp[0]=pack2(a.x); winp[1]=pack2(a.y); winp[2]=pack2(a.z); winp[3]=pack2(a.w);
                    winp[4]=pack2(c.x); winp[5]=pack2(c.y); winp[6]=pack2(c.z); winp[7]=pack2(c.w);
                    winp[8]=pack2(e);
                }
                #pragma unroll
                for (int kx = 0; kx < 6; kx++) {
                    u64 w0 = wp[kx*3 + 0];
                    u64 w1 = wp[kx*3 + 1];
                    u64 w2 = wp[kx*3 + 2];
                    #pragma unroll
                    for (int p = 0; p < 4; p++) {
                        ffma2(acc[p][0], winp[kx+p], w0);
                        ffma2(acc[p][1], winp[kx+p], w1);
                        ffma2(acc[p][2], winp[kx+p], w2);
                    }
                }
            }
            // --- section 2: kx = 6..10, inputs [6..13] ---
            {
                u64 winp[8];
                {
                    float2 a = *(const float2*)(rowp + 6);
                    float4 c = *(const float4*)(rowp + 8);
                    float2 e = *(const float2*)(rowp + 12);
                    winp[0]=pack2(a.x); winp[1]=pack2(a.y);
                    winp[2]=pack2(c.x); winp[3]=pack2(c.y); winp[4]=pack2(c.z); winp[5]=pack2(c.w);
                    winp[6]=pack2(e.x); winp[7]=pack2(e.y);
                }
                #pragma unroll
                for (int kx = 6; kx < 11; kx++) {
                    u64 w0 = wp[kx*3 + 0];
                    u64 w1 = wp[kx*3 + 1];
                    u64 w2 = wp[kx*3 + 2];
                    #pragma unroll
                    for (int p = 0; p < 4; p++) {
                        ffma2(acc[p][0], winp[kx-6+p], w0);
                        ffma2(acc[p][1], winp[kx-6+p], w1);
                        ffma2(acc[p][2], winp[kx-6+p], w2);
                    }
                }
            }
        }
    }

    // unpack, store z, LN partial sums (this half covers 2 gates)
    const int gy = ty0 + ty;
    const int gx = tx0 + tx4;
    float s[2]  = {0.f, 0.f};
    float ss[2] = {0.f, 0.f};
    #pragma unroll
    for (int j = 0; j < 3; j++) {
        float z0[4], z1[4];
        #pragma unroll
        for (int p = 0; p < 4; p++) unpack2(acc[p][j], z0[p], z1[p]);
        int gl0 = (2*j)   / 3;
        int gl1 = (2*j+1) / 3;
        float4 v0, v1;
        v0.x=z0[0]; v0.y=z0[1]; v0.z=z0[2]; v0.w=z0[3];
        v1.x=z1[0]; v1.y=z1[1]; v1.z=z1[2]; v1.w=z1[3];
        #pragma unroll
        for (int p = 0; p < 4; p++) {
            s[gl0]  += z0[p];  ss[gl0] += z0[p]*z0[p];
            s[gl1]  += z1[p];  ss[gl1] += z1[p]*z1[p];
        }
        *(float4*)&g_z[(size_t)(b*12 + half*6 + 2*j    )*GG + gy*G + gx] = v0;
        *(float4*)&g_z[(size_t)(b*12 + half*6 + 2*j + 1)*GG + gy*G + gx] = v1;
    }

    const int lane = tid & 31;
    const int wrp  = tid >> 5;
    #pragma unroll
    for (int g = 0; g < 2; g++) {
        #pragma unroll
        for (int off = 16; off > 0; off >>= 1) {
            s[g]  += __shfl_down_sync(0xFFFFFFFFu, s[g],  off);
            ss[g] += __shfl_down_sync(0xFFFFFFFFu, ss[g], off);
        }
    }
    if (lane == 0) {
        sred[wrp][0] = s[0];  sred[wrp][1] = ss[0];
        sred[wrp][2] = s[1];  sred[wrp][3] = ss[1];
    }
    __syncthreads();
    if (tid < 4) {
        float v = sred[0][tid] + sred[1][tid] + sred[2][tid] + sred[3][tid];
        g_part[((b*8 + tile)*2 + half)*4 + tid] = v;
    }
}

// ---------------- pointwise gate update + PDL (EARLY trigger) -------------------
__global__ __launch_bounds__(256) void k_gates(const float* __restrict__ wci,
                                               const float* __restrict__ wcf,
                                               const float* __restrict__ wco,
                                               const float* __restrict__ lnw,
                                               const float* __restrict__ lnb)
{
    __shared__ float st[8];
    const int b = blockIdx.x / 12;
    const int r = ((blockIdx.x % 12) * 256 + threadIdx.x) * 4;

    // ---- PDL prologue: loads independent of the conv kernel ----
    float4 wi = *(const float4*)&lnw[0*12288 + r];
    float4 bi = *(const float4*)&lnb[0*12288 + r];
    float4 wf = *(const float4*)&lnw[1*12288 + r];
    float4 bf = *(const float4*)&lnb[1*12288 + r];
    float4 wg = *(const float4*)&lnw[2*12288 + r];
    float4 bgv= *(const float4*)&lnb[2*12288 + r];
    float4 wo = *(const float4*)&lnw[3*12288 + r];
    float4 bo = *(const float4*)&lnb[3*12288 + r];
    float4 ci = *(const float4*)&wci[r];
    float4 cf = *(const float4*)&wcf[r];
    float4 co = *(const float4*)&wco[r];
    float4 c4 = *(const float4*)&g_c[b*12288 + r];   // written 2 kernels back — safe

    // ---- wait for conv(t) before touching z / g_part ----
    cudaGridDependencySynchronize();

    const size_t zb = (size_t)b * 12 * GG;
    float4 zi = *(const float4*)&g_z[zb + 0*12288 + r];
    float4 zf = *(const float4*)&g_z[zb + 1*12288 + r];
    float4 zg = *(const float4*)&g_z[zb + 2*12288 + r];
    float4 zo = *(const float4*)&g_z[zb + 3*12288 + r];

    // all conv-dependent reads issued; gates is short and low-occupancy, so the
    // next conv's prologue can co-schedule essentially for free
    cudaTriggerProgrammaticLaunchCompletion();

    if (threadIdx.x < 4) {
        int gt   = threadIdx.x;
        int half = gt >> 1;
        int gl   = gt & 1;
        float s = 0.f, ssum = 0.f;
        #pragma unroll
        for (int tl = 0; tl < 8; tl++) {
            s    += g_part[((b*8 + tl)*2 + half)*4 + gl*2 + 0];
            ssum += g_part[((b*8 + tl)*2 + half)*4 + gl*2 + 1];
        }
        const float inv = 1.f / 12288.f;
        float mu  = s * inv;
        float var = fmaxf(ssum * inv - mu*mu, 0.f);
        st[gt*2 + 0] = mu;
        st[gt*2 + 1] = rsqrtf(var + EPSV);
    }
    __syncthreads();

    float4 cn4, hn4;
    #pragma unroll
    for (int k = 0; k < 4; k++) {
        float vzi = ((const float*)&zi)[k], vzf = ((const float*)&zf)[k];
        float vzg = ((const float*)&zg)[k], vzo = ((const float*)&zo)[k];
        vzi = (vzi - st[0]) * st[1] * ((const float*)&wi)[k] + ((const float*)&bi)[k];
        vzf = (vzf - st[2]) * st[3] * ((const float*)&wf)[k] + ((const float*)&bf)[k];
        vzg = (vzg - st[4]) * st[5] * ((const float*)&wg)[k] + ((const float*)&bgv)[k];
        vzo = (vzo - st[6]) * st[7] * ((const float*)&wo)[k] + ((const float*)&bo)[k];
        float c  = ((const float*)&c4)[k];
        float ig = fsig(vzi + ((const float*)&ci)[k]*c);
        float fg = fsig(vzf + ((const float*)&cf)[k]*c);
        float cn = fg*c + ig*ftanh(vzg);
        float og = fsig(vzo + ((const float*)&co)[k]*cn);
        ((float*)&cn4)[k] = cn;
        ((float*)&hn4)[k] = og * ftanh(cn);
    }
    *(float4*)&g_c[b*12288 + r] = cn4;
    *(float4*)&g_h[b*12288 + r] = hn4;
}

// ---------------- final 37x37 valid conv (+PDL sync at top) ----------------
__global__ __launch_bounds__(128) void k_final(const float* __restrict__ cw,
                                               const float* __restrict__ cb,
                                               float* __restrict__ out)
{
    __shared__ float hs[40*64];
    __shared__ float ws[FK*FK];
    const int b   = blockIdx.x / 7;
    const int seg = blockIdx.x % 7;
    const int oy0 = seg * 4;
    const int tid = threadIdx.x;
    const int ly  = tid / 28;
    const int ox  = tid % 28;

    cudaGridDependencySynchronize();

    float acc = 0.f;
    for (int hc = 0; hc < HID; hc++) {
        __syncthreads();
        for (int i = tid; i < 40*64; i += 128) {
            int r = i / 64;
            hs[i] = g_h[(size_t)(b*HID + hc)*GG + (oy0 + r)*G + (i - r*64)];
        }
        for (int i = tid; i < FK*FK; i += 128) ws[i] = cw[hc*FK*FK + i];
        __syncthreads();
        if (tid < 112) {
            #pragma unroll 1
            for (int ky = 0; ky < FK; ky++) {
                const float* hr = &hs[(ly + ky)*64 + ox];
                const float* wr = &ws[ky*FK];
                float a = 0.f;
                #pragma unroll
                for (int kx = 0; kx < FK; kx++) a = fmaf(hr[kx], wr[kx], a);
                acc += a;
            }
        }
    }
    if (tid < 112) {
        int oy = oy0 + ly;
        out[b*OUTW*OUTW + oy*OUTW + ox] = acc + cb[0];
    }
}

// ---------------- launch (PDL-attributed launches) ----------------
static inline void launch_pdl(void* fn, dim3 grid, dim3 block, void** args)
{
    cudaLaunchConfig_t cfg = {};
    cfg.gridDim  = grid;
    cfg.blockDim = block;
    cfg.stream   = 0;
    cudaLaunchAttribute attr[1];
    attr[0].id = cudaLaunchAttributeProgrammaticStreamSerialization;
    attr[0].val.programmaticStreamSerializationAllowed = 1;
    cfg.attrs    = attr;
    cfg.numAttrs = 1;
    cudaLaunchKernelExC(&cfg, fn, args);
}

extern "C" void kernel_launch(void* const* d_in, const int* in_sizes, int n_in,
                              void* d_out, int out_size)
{
    const float* x   = (const float*)d_in[0];
    const float* Wg  = (const float*)d_in[1];
    const float* bg  = (const float*)d_in[2];
    const float* wci = (const float*)d_in[3];
    const float* wcf = (const float*)d_in[4];
    const float* wco = (const float*)d_in[5];
    const float* lnw = (const float*)d_in[6];
    const float* lnb = (const float*)d_in[7];
    const float* cw  = (const float*)d_in[8];
    const float* cb  = (const float*)d_in[9];
    float* out = (float*)d_out;

    k_init<<<(BB*HID*GG + 255)/256, 256>>>();

    for (int t = 0; t < TT; t++) {
        {
            void* args[] = { (void*)&x, (void*)&Wg, (void*)&bg, (void*)&t };
            launch_pdl((void*)k_conv, dim3(BB*16), dim3(128), args);
        }
        {
            void* args[] = { (void*)&wci, (void*)&wcf, (void*)&wco,
                             (void*)&lnw, (void*)&lnb };
            launch_pdl((void*)k_gates, dim3(BB*12), dim3(256), args);
        }
    }
    {
        void* args[] = { (void*)&cw, (void*)&cb, (void*)&out };
        launch_pdl((void*)k_final, dim3(BB*7), dim3(128), args);
    }
}

// round 16
// speedup vs baseline: 1.0549x; 1.0549x over previous
// Round 16: round-13 PDL champion (2230.7us, implicit triggers only) +
// ky-loop unroll 2 so ptxas software-pipelines next-row smem loads under the
// current row's FFMA2 burst (issue was 53.7% — half the slots empty).
#include <cuda_runtime.h>
#include <math.h>

#define BB   64
#define TT   32
#define HID  3
#define G    64
#define GG   4096
#define NOC  12
#define EPSV 1e-5f
#define FK   37
#define OUTW 28

typedef unsigned long long u64;

// ---------------- packed f32x2 helpers (Blackwell FFMA2 path) ----------------
__device__ __forceinline__ u64 pack2(float x) {
    u64 d; unsigned u = __float_as_uint(x);
    asm("mov.b64 %0, {%1, %1};" : "=l"(d) : "r"(u));
    return d;
}
__device__ __forceinline__ u64 packlh(float lo, float hi) {
    u64 d; unsigned a = __float_as_uint(lo), b = __float_as_uint(hi);
    asm("mov.b64 %0, {%1, %2};" : "=l"(d) : "r"(a), "r"(b));
    return d;
}
__device__ __forceinline__ void ffma2(u64 &acc, u64 a, u64 b) {
    asm("fma.rn.f32x2 %0, %1, %2, %0;" : "+l"(acc) : "l"(a), "l"(b));
}
__device__ __forceinline__ void unpack2(u64 d, float &lo, float &hi) {
    unsigned a, b;
    asm("mov.b64 {%0, %1}, %2;" : "=r"(a), "=r"(b) : "l"(d));
    lo = __uint_as_float(a); hi = __uint_as_float(b);
}

// fast sigmoid / tanh (~1e-6 rel err)
__device__ __forceinline__ float fsig(float x) {
    float t, r;
    asm("mul.f32 %0, %1, 0fBFB8AA3B;" : "=f"(t) : "f"(x));
    asm("ex2.approx.f32 %0, %0;" : "+f"(t));
    asm("add.f32 %0, %0, 0f3F800000;" : "+f"(t));
    asm("rcp.approx.f32 %0, %1;" : "=f"(r) : "f"(t));
    return r;
}
__device__ __forceinline__ float ftanh(float x) {
    return fmaf(2.f, fsig(2.f * x), -1.f);
}

// ---------------- static device scratch ----------------
__device__ float g_h[BB*HID*GG];
__device__ float g_c[BB*HID*GG];
__device__ float g_z[BB*NOC*GG];
__device__ float g_part[BB*8*2*4];   // [b][tile][half][gate_local*2+which]

__global__ void k_init() {
    int i = blockIdx.x * blockDim.x + threadIdx.x;
    if (i < BB*HID*GG) { g_h[i] = 0.f; g_c[i] = 0.f; }
}

// ---------------- per-step conv, oc-halves + PDL (implicit trigger) ------------
// grid: BB*16 blocks = (b, tile 0..7, half 0..1); 16x32 output tile, 128 thr, 4 px
__global__ __launch_bounds__(128, 7) void k_conv(const float* __restrict__ x,
                                                 const float* __restrict__ Wg,
                                                 const float* __restrict__ bg,
                                                 int t)
{
    __shared__ __align__(16) float ts[4*26*44];     // input tile, row stride 44 (18.3KB)
    __shared__ __align__(16) float wsm[4*121*6];    // weights [ic][ky][kx][ocl] (11.6KB)
    __shared__ float sred[4][4];

    const int tid  = threadIdx.x;
    const int b    = blockIdx.x >> 4;
    const int rem  = blockIdx.x & 15;
    const int tile = rem >> 1;                    // 0..7: 4 row-tiles x 2 col-tiles
    const int half = rem & 1;
    const int ty0  = (tile >> 1) << 4;            // 0,16,32,48
    const int tx0  = (tile & 1) << 5;             // 0,32

    // ---- PDL prologue (independent of predecessor kernel) ----
    for (int i = tid; i < 4*121*6; i += 128) {
        int ocl = i % 6;
        int k   = i / 6;
        int ic  = k / 121;
        int kk  = k - ic*121;
        wsm[i] = Wg[((half*6 + ocl)*4 + ic)*121 + kk];
    }
    const float* xb = x + (size_t)(b*TT + t) * GG;
    for (int i = tid; i < 1092; i += 128) {
        int r  = i / 42;
        int cc = i - r*42;
        int gy = ty0 - 5 + r;
        int gx = tx0 - 5 + cc;
        float v = 0.f;
        if (gy >= 0 && gy < G && gx >= 0 && gx < G) v = xb[gy*G + gx];
        ts[r*44 + cc] = v;
    }

    // ---- wait for predecessor (gates t-1 / init) before touching g_h ----
    cudaGridDependencySynchronize();

    // ic = 1..3 tile rows from g_h
    for (int i = tid; i < 3*1092; i += 128) {
        int ic  = i / 1092 + 1;
        int rm  = i - (ic - 1)*1092;
        int r   = rm / 42;
        int cc  = rm - r*42;
        int gy = ty0 - 5 + r;
        int gx = tx0 - 5 + cc;
        float v = 0.f;
        if (gy >= 0 && gy < G && gx >= 0 && gx < G)
            v = g_h[(b*HID + ic - 1)*GG + gy*G + gx];
        ts[(ic*26 + r)*44 + cc] = v;
    }
    __syncthreads();

    const int ty  = tid >> 3;           // 0..15
    const int tx4 = (tid & 7) << 2;     // 0,4,..,28

    u64 acc[4][3];
    #pragma unroll
    for (int j = 0; j < 3; j++) {
        u64 bp = packlh(bg[half*6 + 2*j], bg[half*6 + 2*j + 1]);
        #pragma unroll
        for (int p = 0; p < 4; p++) acc[p][j] = bp;
    }

    #pragma unroll 1
    for (int ic = 0; ic < 4; ic++) {
        #pragma unroll 2
        for (int ky = 0; ky < 11; ky++) {
            const float* rowp = &ts[(ic*26 + ty + ky)*44 + tx4];
            const u64*   wp   = (const u64*)&wsm[(ic*121 + ky*11)*6];

            // --- section 1: kx = 0..5, inputs [0..8] ---
            {
                u64 winp[9];
                {
                    float4 a = ((const float4*)rowp)[0];
                    float4 c = ((const float4*)rowp)[1];
                    float  e = rowp[8];
                    winp[0]=pack2(a.x); winp[1]=pack2(a.y); winp[2]=pack2(a.z); winp[3]=pack2(a.w);
                    winp[4]=pack2(c.x); winp[5]=pack2(c.y); winp[6]=pack2(c.z); winp[7]=pack2(c.w);
                    winp[8]=pack2(e);
                }
                #pragma unroll
                for (int kx = 0; kx < 6; kx++) {
                    u64 w0 = wp[kx*3 + 0];
                    u64 w1 = wp[kx*3 + 1];
                    u64 w2 = wp[kx*3 + 2];
                    #pragma unroll
                    for (int p = 0; p < 4; p++) {
                        ffma2(acc[p][0], winp[kx+p], w0);
                        ffma2(acc[p][1], winp[kx+p], w1);
                        ffma2(acc[p][2], winp[kx+p], w2);
                    }
                }
            }
            // --- section 2: kx = 6..10, inputs [6..13] ---
            {
                u64 winp[8];
                {
                    float2 a = *(const float2*)(rowp + 6);
                    float4 c = *(const float4*)(rowp + 8);
                    float2 e = *(const float2*)(rowp + 12);
                    winp[0]=pack2(a.x); winp[1]=pack2(a.y);
                    winp[2]=pack2(c.x); winp[3]=pack2(c.y); winp[4]=pack2(c.z); winp[5]=pack2(c.w);
                    winp[6]=pack2(e.x); winp[7]=pack2(e.y);
                }
                #pragma unroll
                for (int kx = 6; kx < 11; kx++) {
                    u64 w0 = wp[kx*3 + 0];
                    u64 w1 = wp[kx*3 + 1];
                    u64 w2 = wp[kx*3 + 2];
                    #pragma unroll
                    for (int p = 0; p < 4; p++) {
                        ffma2(acc[p][0], winp[kx-6+p], w0);
                        ffma2(acc[p][1], winp[kx-6+p], w1);
                        ffma2(acc[p][2], winp[kx-6+p], w2);
                    }
                }
            }
        }
    }

    // unpack, store z, LN partial sums (this half covers 2 gates)
    const int gy = ty0 + ty;
    const int gx = tx0 + tx4;
    float s[2]  = {0.f, 0.f};
    float ss[2] = {0.f, 0.f};
    #pragma unroll
    for (int j = 0; j < 3; j++) {
        float z0[4], z1[4];
        #pragma unroll
        for (int p = 0; p < 4; p++) unpack2(acc[p][j], z0[p], z1[p]);
        int gl0 = (2*j)   / 3;
        int gl1 = (2*j+1) / 3;
        float4 v0, v1;
        v0.x=z0[0]; v0.y=z0[1]; v0.z=z0[2]; v0.w=z0[3];
        v1.x=z1[0]; v1.y=z1[1]; v1.z=z1[2]; v1.w=z1[3];
        #pragma unroll
        for (int p = 0; p < 4; p++) {
            s[gl0]  += z0[p];  ss[gl0] += z0[p]*z0[p];
            s[gl1]  += z1[p];  ss[gl1] += z1[p]*z1[p];
        }
        *(float4*)&g_z[(size_t)(b*12 + half*6 + 2*j    )*GG + gy*G + gx] = v0;
        *(float4*)&g_z[(size_t)(b*12 + half*6 + 2*j + 1)*GG + gy*G + gx] = v1;
    }

    const int lane = tid & 31;
    const int wrp  = tid >> 5;
    #pragma unroll
    for (int g = 0; g < 2; g++) {
        #pragma unroll
        for (int off = 16; off > 0; off >>= 1) {
            s[g]  += __shfl_down_sync(0xFFFFFFFFu, s[g],  off);
            ss[g] += __shfl_down_sync(0xFFFFFFFFu, ss[g], off);
        }
    }
    if (lane == 0) {
        sred[wrp][0] = s[0];  sred[wrp][1] = ss[0];
        sred[wrp][2] = s[1];  sred[wrp][3] = ss[1];
    }
    __syncthreads();
    if (tid < 4) {
        float v = sred[0][tid] + sred[1][tid] + sred[2][tid] + sred[3][tid];
        g_part[((b*8 + tile)*2 + half)*4 + tid] = v;
    }
}

// ---------------- pointwise gate update + PDL (implicit trigger) ----------------
__global__ __launch_bounds__(256) void k_gates(const float* __restrict__ wci,
                                               const float* __restrict__ wcf,
                                               const float* __restrict__ wco,
                                               const float* __restrict__ lnw,
                                               const float* __restrict__ lnb)
{
    __shared__ float st[8];
    const int b = blockIdx.x / 12;
    const int r = ((blockIdx.x % 12) * 256 + threadIdx.x) * 4;

    // ---- PDL prologue: loads independent of the conv kernel ----
    float4 wi = *(const float4*)&lnw[0*12288 + r];
    float4 bi = *(const float4*)&lnb[0*12288 + r];
    float4 wf = *(const float4*)&lnw[1*12288 + r];
    float4 bf = *(const float4*)&lnb[1*12288 + r];
    float4 wg = *(const float4*)&lnw[2*12288 + r];
    float4 bgv= *(const float4*)&lnb[2*12288 + r];
    float4 wo = *(const float4*)&lnw[3*12288 + r];
    float4 bo = *(const float4*)&lnb[3*12288 + r];
    float4 ci = *(const float4*)&wci[r];
    float4 cf = *(const float4*)&wcf[r];
    float4 co = *(const float4*)&wco[r];
    float4 c4 = *(const float4*)&g_c[b*12288 + r];   // written 2 kernels back — safe

    // ---- wait for conv(t) before touching z / g_part ----
    cudaGridDependencySynchronize();

    const size_t zb = (size_t)b * 12 * GG;
    float4 zi = *(const float4*)&g_z[zb + 0*12288 + r];
    float4 zf = *(const float4*)&g_z[zb + 1*12288 + r];
    float4 zg = *(const float4*)&g_z[zb + 2*12288 + r];
    float4 zo = *(const float4*)&g_z[zb + 3*12288 + r];

    if (threadIdx.x < 4) {
        int gt   = threadIdx.x;
        int half = gt >> 1;
        int gl   = gt & 1;
        float s = 0.f, ssum = 0.f;
        #pragma unroll
        for (int tl = 0; tl < 8; tl++) {
            s    += g_part[((b*8 + tl)*2 + half)*4 + gl*2 + 0];
            ssum += g_part[((b*8 + tl)*2 + half)*4 + gl*2 + 1];
        }
        const float inv = 1.f / 12288.f;
        float mu  = s * inv;
        float var = fmaxf(ssum * inv - mu*mu, 0.f);
        st[gt*2 + 0] = mu;
        st[gt*2 + 1] = rsqrtf(var + EPSV);
    }
    __syncthreads();

    float4 cn4, hn4;
    #pragma unroll
    for (int k = 0; k < 4; k++) {
        float vzi = ((const float*)&zi)[k], vzf = ((const float*)&zf)[k];
        float vzg = ((const float*)&zg)[k], vzo = ((const float*)&zo)[k];
        vzi = (vzi - st[0]) * st[1] * ((const float*)&wi)[k] + ((const float*)&bi)[k];
        vzf = (vzf - st[2]) * st[3] * ((const float*)&wf)[k] + ((const float*)&bf)[k];
        vzg = (vzg - st[4]) * st[5] * ((const float*)&wg)[k] + ((const float*)&bgv)[k];
        vzo = (vzo - st[6]) * st[7] * ((const float*)&wo)[k] + ((const float*)&bo)[k];
        float c  = ((const float*)&c4)[k];
        float ig = fsig(vzi + ((const float*)&ci)[k]*c);
        float fg = fsig(vzf + ((const float*)&cf)[k]*c);
        float cn = fg*c + ig*ftanh(vzg);
        float og = fsig(vzo + ((const float*)&co)[k]*cn);
        ((float*)&cn4)[k] = cn;
        ((float*)&hn4)[k] = og * ftanh(cn);
    }
    *(float4*)&g_c[b*12288 + r] = cn4;
    *(float4*)&g_h[b*12288 + r] = hn4;
}

// ---------------- final 37x37 valid conv (+PDL sync at top) ----------------
__global__ __launch_bounds__(128) void k_final(const float* __restrict__ cw,
                                               const float* __restrict__ cb,
                                               float* __restrict__ out)
{
    __shared__ float hs[40*64];
    __shared__ float ws[FK*FK];
    const int b   = blockIdx.x / 7;
    const int seg = blockIdx.x % 7;
    const int oy0 = seg * 4;
    const int tid = threadIdx.x;
    const int ly  = tid / 28;
    const int ox  = tid % 28;

    cudaGridDependencySynchronize();

    float acc = 0.f;
    for (int hc = 0; hc < HID; hc++) {
        __syncthreads();
        for (int i = tid; i < 40*64; i += 128) {
            int r = i / 64;
            hs[i] = g_h[(size_t)(b*HID + hc)*GG + (oy0 + r)*G + (i - r*64)];
        }
        for (int i = tid; i < FK*FK; i += 128) ws[i] = cw[hc*FK*FK + i];
        __syncthreads();
        if (tid < 112) {
            #pragma unroll 1
            for (int ky = 0; ky < FK; ky++) {
                const float* hr = &hs[(ly + ky)*64 + ox];
                const float* wr = &ws[ky*FK];
                float a = 0.f;
                #pragma unroll
                for (int kx = 0; kx < FK; kx++) a = fmaf(hr[kx], wr[kx], a);
                acc += a;
            }
        }
    }
    if (tid < 112) {
        int oy = oy0 + ly;
        out[b*OUTW*OUTW + oy*OUTW + ox] = acc + cb[0];
    }
}

// ---------------- launch (PDL-attributed launches) ----------------
static inline void launch_pdl(void* fn, dim3 grid, dim3 block, void** args)
{
    cudaLaunchConfig_t cfg = {};
    cfg.gridDim  = grid;
    cfg.blockDim = block;
    cfg.stream   = 0;
    cudaLaunchAttribute attr[1];
    attr[0].id = cudaLaunchAttributeProgrammaticStreamSerialization;
    attr[0].val.programmaticStreamSerializationAllowed = 1;
    cfg.attrs    = attr;
    cfg.numAttrs = 1;
    cudaLaunchKernelExC(&cfg, fn, args);
}

extern "C" void kernel_launch(void* const* d_in, const int* in_sizes, int n_in,
                              void* d_out, int out_size)
{
    const float* x   = (const float*)d_in[0];
    const float* Wg  = (const float*)d_in[1];
    const float* bg  = (const float*)d_in[2];
    const float* wci = (const float*)d_in[3];
    const float* wcf = (const float*)d_in[4];
    const float* wco = (const float*)d_in[5];
    const float* lnw = (const float*)d_in[6];
    const float* lnb = (const float*)d_in[7];
    const float* cw  = (const float*)d_in[8];
    const float* cb  = (const float*)d_in[9];
    float* out = (float*)d_out;

    k_init<<<(BB*HID*GG + 255)/256, 256>>>();

    for (int t = 0; t < TT; t++) {
        {
            void* args[] = { (void*)&x, (void*)&Wg, (void*)&bg, (void*)&t };
            launch_pdl((void*)k_conv, dim3(BB*16), dim3(128), args);
        }
        {
            void* args[] = { (void*)&wci, (void*)&wcf, (void*)&wco,
                             (void*)&lnw, (void*)&lnb };
            launch_pdl((void*)k_gates, dim3(BB*12), dim3(256), args);
        }
    }
    {
        void* args[] = { (void*)&cw, (void*)&cb, (void*)&out };
        launch_pdl((void*)k_final, dim3(BB*7), dim3(128), args);
    }
}

// round 17
// speedup vs baseline: 1.0867x; 1.0301x over previous
// Round 17: revert to the round-13 champion VERBATIM (2230.7us) and re-verify.
// Post-mortem of rounds 14-16: every perturbation (early triggers both sides,
// ky unroll 2) regressed or was neutral; implicit-trigger PDL + round-4 conv
// is the measured optimum. Per-step wall time == conv ncu duration (69.7us):
// k_gates and all launch seams are fully hidden.
#include <cuda_runtime.h>
#include <math.h>

#define BB   64
#define TT   32
#define HID  3
#define G    64
#define GG   4096
#define NOC  12
#define EPSV 1e-5f
#define FK   37
#define OUTW 28

typedef unsigned long long u64;

// ---------------- packed f32x2 helpers (Blackwell FFMA2 path) ----------------
__device__ __forceinline__ u64 pack2(float x) {
    u64 d; unsigned u = __float_as_uint(x);
    asm("mov.b64 %0, {%1, %1};" : "=l"(d) : "r"(u));
    return d;
}
__device__ __forceinline__ u64 packlh(float lo, float hi) {
    u64 d; unsigned a = __float_as_uint(lo), b = __float_as_uint(hi);
    asm("mov.b64 %0, {%1, %2};" : "=l"(d) : "r"(a), "r"(b));
    return d;
}
__device__ __forceinline__ void ffma2(u64 &acc, u64 a, u64 b) {
    asm("fma.rn.f32x2 %0, %1, %2, %0;" : "+l"(acc) : "l"(a), "l"(b));
}
__device__ __forceinline__ void unpack2(u64 d, float &lo, float &hi) {
    unsigned a, b;
    asm("mov.b64 {%0, %1}, %2;" : "=r"(a), "=r"(b) : "l"(d));
    lo = __uint_as_float(a); hi = __uint_as_float(b);
}

// fast sigmoid / tanh (~1e-6 rel err)
__device__ __forceinline__ float fsig(float x) {
    float t, r;
    asm("mul.f32 %0, %1, 0fBFB8AA3B;" : "=f"(t) : "f"(x));
    asm("ex2.approx.f32 %0, %0;" : "+f"(t));
    asm("add.f32 %0, %0, 0f3F800000;" : "+f"(t));
    asm("rcp.approx.f32 %0, %1;" : "=f"(r) : "f"(t));
    return r;
}
__device__ __forceinline__ float ftanh(float x) {
    return fmaf(2.f, fsig(2.f * x), -1.f);
}

// ---------------- static device scratch ----------------
__device__ float g_h[BB*HID*GG];
__device__ float g_c[BB*HID*GG];
__device__ float g_z[BB*NOC*GG];
__device__ float g_part[BB*8*2*4];   // [b][tile][half][gate_local*2+which]

__global__ void k_init() {
    int i = blockIdx.x * blockDim.x + threadIdx.x;
    if (i < BB*HID*GG) { g_h[i] = 0.f; g_c[i] = 0.f; }
}

// ---------------- per-step conv, oc-halves + PDL (implicit trigger) ------------
// grid: BB*16 blocks = (b, tile 0..7, half 0..1); 16x32 output tile, 128 thr, 4 px
__global__ __launch_bounds__(128, 7) void k_conv(const float* __restrict__ x,
                                                 const float* __restrict__ Wg,
                                                 const float* __restrict__ bg,
                                                 int t)
{
    __shared__ __align__(16) float ts[4*26*44];     // input tile, row stride 44 (18.3KB)
    __shared__ __align__(16) float wsm[4*121*6];    // weights [ic][ky][kx][ocl] (11.6KB)
    __shared__ float sred[4][4];

    const int tid  = threadIdx.x;
    const int b    = blockIdx.x >> 4;
    const int rem  = blockIdx.x & 15;
    const int tile = rem >> 1;                    // 0..7: 4 row-tiles x 2 col-tiles
    const int half = rem & 1;
    const int ty0  = (tile >> 1) << 4;            // 0,16,32,48
    const int tx0  = (tile & 1) << 5;             // 0,32

    // ---- PDL prologue (independent of predecessor kernel) ----
    for (int i = tid; i < 4*121*6; i += 128) {
        int ocl = i % 6;
        int k   = i / 6;
        int ic  = k / 121;
        int kk  = k - ic*121;
        wsm[i] = Wg[((half*6 + ocl)*4 + ic)*121 + kk];
    }
    const float* xb = x + (size_t)(b*TT + t) * GG;
    for (int i = tid; i < 1092; i += 128) {
        int r  = i / 42;
        int cc = i - r*42;
        int gy = ty0 - 5 + r;
        int gx = tx0 - 5 + cc;
        float v = 0.f;
        if (gy >= 0 && gy < G && gx >= 0 && gx < G) v = xb[gy*G + gx];
        ts[r*44 + cc] = v;
    }

    // ---- wait for predecessor (gates t-1 / init) before touching g_h ----
    cudaGridDependencySynchronize();

    // ic = 1..3 tile rows from g_h
    for (int i = tid; i < 3*1092; i += 128) {
        int ic  = i / 1092 + 1;
        int rm  = i - (ic - 1)*1092;
        int r   = rm / 42;
        int cc  = rm - r*42;
        int gy = ty0 - 5 + r;
        int gx = tx0 - 5 + cc;
        float v = 0.f;
        if (gy >= 0 && gy < G && gx >= 0 && gx < G)
            v = g_h[(b*HID + ic - 1)*GG + gy*G + gx];
        ts[(ic*26 + r)*44 + cc] = v;
    }
    __syncthreads();

    const int ty  = tid >> 3;           // 0..15
    const int tx4 = (tid & 7) << 2;     // 0,4,..,28

    u64 acc[4][3];
    #pragma unroll
    for (int j = 0; j < 3; j++) {
        u64 bp = packlh(bg[half*6 + 2*j], bg[half*6 + 2*j + 1]);
        #pragma unroll
        for (int p = 0; p < 4; p++) acc[p][j] = bp;
    }

    #pragma unroll 1
    for (int ic = 0; ic < 4; ic++) {
        #pragma unroll 1
        for (int ky = 0; ky < 11; ky++) {
            const float* rowp = &ts[(ic*26 + ty + ky)*44 + tx4];
            const u64*   wp   = (const u64*)&wsm[(ic*121 + ky*11)*6];

            // --- section 1: kx = 0..5, inputs [0..8] ---
            {
                u64 winp[9];
                {
                    float4 a = ((const float4*)rowp)[0];
                    float4 c = ((const float4*)rowp)[1];
                    float  e = rowp[8];
                    winp[0]=pack2(a.x); winp[1]=pack2(a.y); winp[2]=pack2(a.z); winp[3]=pack2(a.w);
                    winp[4]=pack2(c.x); winp[5]=pack2(c.y); winp[6]=pack2(c.z); winp[7]=pack2(c.w);
                    winp[8]=pack2(e);
                }
                #pragma unroll
                for (int kx = 0; kx < 6; kx++) {
                    u64 w0 = wp[kx*3 + 0];
                    u64 w1 = wp[kx*3 + 1];
                    u64 w2 = wp[kx*3 + 2];
                    #pragma unroll
                    for (int p = 0; p < 4; p++) {
                        ffma2(acc[p][0], winp[kx+p], w0);
                        ffma2(acc[p][1], winp[kx+p], w1);
                        ffma2(acc[p][2], winp[kx+p], w2);
                    }
                }
            }
            // --- section 2: kx = 6..10, inputs [6..13] ---
            {
                u64 winp[8];
                {
                    float2 a = *(const float2*)(rowp + 6);
                    float4 c = *(const float4*)(rowp + 8);
                    float2 e = *(const float2*)(rowp + 12);
                    winp[0]=pack2(a.x); winp[1]=pack2(a.y);
                    winp[2]=pack2(c.x); winp[3]=pack2(c.y); winp[4]=pack2(c.z); winp[5]=pack2(c.w);
                    winp[6]=pack2(e.x); winp[7]=pack2(e.y);
                }
                #pragma unroll
                for (int kx = 6; kx < 11; kx++) {
                    u64 w0 = wp[kx*3 + 0];
                    u64 w1 = wp[kx*3 + 1];
                    u64 w2 = wp[kx*3 + 2];
                    #pragma unroll
                    for (int p = 0; p < 4; p++) {
                        ffma2(acc[p][0], winp[kx-6+p], w0);
                        ffma2(acc[p][1], winp[kx-6+p], w1);
                        ffma2(acc[p][2], winp[kx-6+p], w2);
                    }
                }
            }
        }
    }

    // unpack, store z, LN partial sums (this half covers 2 gates)
    const int gy = ty0 + ty;
    const int gx = tx0 + tx4;
    float s[2]  = {0.f, 0.f};
    float ss[2] = {0.f, 0.f};
    #pragma unroll
    for (int j = 0; j < 3; j++) {
        float z0[4], z1[4];
        #pragma unroll
        for (int p = 0; p < 4; p++) unpack2(acc[p][j], z0[p], z1[p]);
        int gl0 = (2*j)   / 3;
        int gl1 = (2*j+1) / 3;
        float4 v0, v1;
        v0.x=z0[0]; v0.y=z0[1]; v0.z=z0[2]; v0.w=z0[3];
        v1.x=z1[0]; v1.y=z1[1]; v1.z=z1[2]; v1.w=z1[3];
        #pragma unroll
        for (int p = 0; p < 4; p++) {
            s[gl0]  += z0[p];  ss[gl0] += z0[p]*z0[p];
            s[gl1]  += z1[p];  ss[gl1] += z1[p]*z1[p];
        }
        *(float4*)&g_z[(size_t)(b*12 + half*6 + 2*j    )*GG + gy*G + gx] = v0;
        *(float4*)&g_z[(size_t)(b*12 + half*6 + 2*j + 1)*GG + gy*G + gx] = v1;
    }

    const int lane = tid & 31;
    const int wrp  = tid >> 5;
    #pragma unroll
    for (int g = 0; g < 2; g++) {
        #pragma unroll
        for (int off = 16; off > 0; off >>= 1) {
            s[g]  += __shfl_down_sync(0xFFFFFFFFu, s[g],  off);
            ss[g] += __shfl_down_sync(0xFFFFFFFFu, ss[g], off);
        }
    }
    if (lane == 0) {
        sred[wrp][0] = s[0];  sred[wrp][1] = ss[0];
        sred[wrp][2] = s[1];  sred[wrp][3] = ss[1];
    }
    __syncthreads();
    if (tid < 4) {
        float v = sred[0][tid] + sred[1][tid] + sred[2][tid] + sred[3][tid];
        g_part[((b*8 + tile)*2 + half)*4 + tid] = v;
    }
}

// ---------------- pointwise gate update + PDL (implicit trigger) ----------------
__global__ __launch_bounds__(256) void k_gates(const float* __restrict__ wci,
                                               const float* __restrict__ wcf,
                                               const float* __restrict__ wco,
                                               const float* __restrict__ lnw,
                                               const float* __restrict__ lnb)
{
    __shared__ float st[8];
    const int b = blockIdx.x / 12;
    const int r = ((blockIdx.x % 12) * 256 + threadIdx.x) * 4;

    // ---- PDL prologue: loads independent of the conv kernel ----
    float4 wi = *(const float4*)&lnw[0*12288 + r];
    float4 bi = *(const float4*)&lnb[0*12288 + r];
    float4 wf = *(const float4*)&lnw[1*12288 + r];
    float4 bf = *(const float4*)&lnb[1*12288 + r];
    float4 wg = *(const float4*)&lnw[2*12288 + r];
    float4 bgv= *(const float4*)&lnb[2*12288 + r];
    float4 wo = *(const float4*)&lnw[3*12288 + r];
    float4 bo = *(const float4*)&lnb[3*12288 + r];
    float4 ci = *(const float4*)&wci[r];
    float4 cf = *(const float4*)&wcf[r];
    float4 co = *(const float4*)&wco[r];
    float4 c4 = *(const float4*)&g_c[b*12288 + r];   // written 2 kernels back — safe

    // ---- wait for conv(t) before touching z / g_part ----
    cudaGridDependencySynchronize();

    const size_t zb = (size_t)b * 12 * GG;
    float4 zi = *(const float4*)&g_z[zb + 0*12288 + r];
    float4 zf = *(const float4*)&g_z[zb + 1*12288 + r];
    float4 zg = *(const float4*)&g_z[zb + 2*12288 + r];
    float4 zo = *(const float4*)&g_z[zb + 3*12288 + r];

    if (threadIdx.x < 4) {
        int gt   = threadIdx.x;
        int half = gt >> 1;
        int gl   = gt & 1;
        float s = 0.f, ssum = 0.f;
        #pragma unroll
        for (int tl = 0; tl < 8; tl++) {
            s    += g_part[((b*8 + tl)*2 + half)*4 + gl*2 + 0];
            ssum += g_part[((b*8 + tl)*2 + half)*4 + gl*2 + 1];
        }
        const float inv = 1.f / 12288.f;
        float mu  = s * inv;
        float var = fmaxf(ssum * inv - mu*mu, 0.f);
        st[gt*2 + 0] = mu;
        st[gt*2 + 1] = rsqrtf(var + EPSV);
    }
    __syncthreads();

    float4 cn4, hn4;
    #pragma unroll
    for (int k = 0; k < 4; k++) {
        float vzi = ((const float*)&zi)[k], vzf = ((const float*)&zf)[k];
        float vzg = ((const float*)&zg)[k], vzo = ((const float*)&zo)[k];
        vzi = (vzi - st[0]) * st[1] * ((const float*)&wi)[k] + ((const float*)&bi)[k];
        vzf = (vzf - st[2]) * st[3] * ((const float*)&wf)[k] + ((const float*)&bf)[k];
        vzg = (vzg - st[4]) * st[5] * ((const float*)&wg)[k] + ((const float*)&bgv)[k];
        vzo = (vzo - st[6]) * st[7] * ((const float*)&wo)[k] + ((const float*)&bo)[k];
        float c  = ((const float*)&c4)[k];
        float ig = fsig(vzi + ((const float*)&ci)[k]*c);
        float fg = fsig(vzf + ((const float*)&cf)[k]*c);
        float cn = fg*c + ig*ftanh(vzg);
        float og = fsig(vzo + ((const float*)&co)[k]*cn);
        ((float*)&cn4)[k] = cn;
        ((float*)&hn4)[k] = og * ftanh(cn);
    }
    *(float4*)&g_c[b*12288 + r] = cn4;
    *(float4*)&g_h[b*12288 + r] = hn4;
}

// ---------------- final 37x37 valid conv (+PDL sync at top) ----------------
__global__ __launch_bounds__(128) void k_final(const float* __restrict__ cw,
                                               const float* __restrict__ cb,
                                               float* __restrict__ out)
{
    __shared__ float hs[40*64];
    __shared__ float ws[FK*FK];
    const int b   = blockIdx.x / 7;
    const int seg = blockIdx.x % 7;
    const int oy0 = seg * 4;
    const int tid = threadIdx.x;
    const int ly  = tid / 28;
    const int ox  = tid % 28;

    cudaGridDependencySynchronize();

    float acc = 0.f;
    for (int hc = 0; hc < HID; hc++) {
        __syncthreads();
        for (int i = tid; i < 40*64; i += 128) {
            int r = i / 64;
            hs[i] = g_h[(size_t)(b*HID + hc)*GG + (oy0 + r)*G + (i - r*64)];
        }
        for (int i = tid; i < FK*FK; i += 128) ws[i] = cw[hc*FK*FK + i];
        __syncthreads();
        if (tid < 112) {
            #pragma unroll 1
            for (int ky = 0; ky < FK; ky++) {
                const float* hr = &hs[(ly + ky)*64 + ox];
                const float* wr = &ws[ky*FK];
                float a = 0.f;
                #pragma unroll
                for (int kx = 0; kx < FK; kx++) a = fmaf(hr[kx], wr[kx], a);
                acc += a;
            }
        }
    }
    if (tid < 112) {
        int oy = oy0 + ly;
        out[b*OUTW*OUTW + oy*OUTW + ox] = acc + cb[0];
    }
}

// ---------------- launch (PDL-attributed launches) ----------------
static inline void launch_pdl(void* fn, dim3 grid, dim3 block, void** args)
{
    cudaLaunchConfig_t cfg = {};
    cfg.gridDim  = grid;
    cfg.blockDim = block;
    cfg.stream   = 0;
    cudaLaunchAttribute attr[1];
    attr[0].id = cudaLaunchAttributeProgrammaticStreamSerialization;
    attr[0].val.programmaticStreamSerializationAllowed = 1;
    cfg.attrs    = attr;
    cfg.numAttrs = 1;
    cudaLaunchKernelExC(&cfg, fn, args);
}

extern "C" void kernel_launch(void* const* d_in, const int* in_sizes, int n_in,
                              void* d_out, int out_size)
{
    const float* x   = (const float*)d_in[0];
    const float* Wg  = (const float*)d_in[1];
    const float* bg  = (const float*)d_in[2];
    const float* wci = (const float*)d_in[3];
    const float* wcf = (const float*)d_in[4];
    const float* wco = (const float*)d_in[5];
    const float* lnw = (const float*)d_in[6];
    const float* lnb = (const float*)d_in[7];
    const float* cw  = (const float*)d_in[8];
    const float* cb  = (const float*)d_in[9];
    float* out = (float*)d_out;

    k_init<<<(BB*HID*GG + 255)/256, 256>>>();

    for (int t = 0; t < TT; t++) {
        {
            void* args[] = { (void*)&x, (void*)&Wg, (void*)&bg, (void*)&t };
            launch_pdl((void*)k_conv, dim3(BB*16), dim3(128), args);
        }
        {
            void* args[] = { (void*)&wci, (void*)&wcf, (void*)&wco,
                             (void*)&lnw, (void*)&lnb };
            launch_pdl((void*)k_gates, dim3(BB*12), dim3(256), args);
        }
    }
    {
        void* args[] = { (void*)&cw, (void*)&cb, (void*)&out };
        launch_pdl((void*)k_final, dim3(BB*7), dim3(128), args);
    }
}